// round 1
// baseline (speedup 1.0000x reference)
#include <cuda_runtime.h>
#include <cstdint>
#include <cstddef>

#define BB   64
#define TT   256
#define DD   1024
#define HH   1024
#define G4   4096   // 4*H

// ---------------- scratch (device globals; no allocation allowed) ----------------
__device__ float g_G0[TT * BB * G4];     // [t][b][4H] precomputed x@Wx0 + b0  (256 MB)
__device__ float g_Wx0c[DD * G4];        // tf32-rounded weights
__device__ float g_Wh0c[HH * G4];
__device__ float g_Wx1c[HH * G4];
__device__ float g_Wh1c[HH * G4];
__device__ float g_h0[2][BB * HH];       // ping-pong hidden states
__device__ float g_h1[2][BB * HH];
__device__ float g_c0[BB * HH];
__device__ float g_c1[BB * HH];

// ---------------- helpers ----------------
__device__ __forceinline__ uint32_t f2tf(float x) {
    uint32_t r;
    asm("cvt.rna.tf32.f32 %0, %1;" : "=r"(r) : "f"(x));
    return r;
}

__device__ __forceinline__ void mma8(float* d, const uint32_t* a, const uint32_t* b) {
    asm volatile(
        "mma.sync.aligned.m16n8k8.row.col.f32.tf32.tf32.f32 "
        "{%0,%1,%2,%3}, {%4,%5,%6,%7}, {%8,%9}, {%0,%1,%2,%3};"
        : "+f"(d[0]), "+f"(d[1]), "+f"(d[2]), "+f"(d[3])
        : "r"(a[0]), "r"(a[1]), "r"(a[2]), "r"(a[3]), "r"(b[0]), "r"(b[1]));
}

__device__ __forceinline__ float sigf(float x)  { return 1.f / (1.f + __expf(-x)); }
__device__ __forceinline__ float tanhf_(float x){ return 2.f / (1.f + __expf(-2.f * x)) - 1.f; }

// ---------------- weight tf32 pre-rounding ----------------
__global__ void convert_all_kernel(const float* __restrict__ Wx0, const float* __restrict__ Wh0,
                                   const float* __restrict__ Wx1, const float* __restrict__ Wh1) {
    const int n1 = 1 << 22;                 // 1024*4096
    const int stride = gridDim.x * blockDim.x;
    for (int i = blockIdx.x * blockDim.x + threadIdx.x; i < 4 * n1; i += stride) {
        int w = i >> 22;
        int j = i & (n1 - 1);
        float v;
        float* dst;
        if (w == 0)      { v = Wx0[j]; dst = g_Wx0c; }
        else if (w == 1) { v = Wh0[j]; dst = g_Wh0c; }
        else if (w == 2) { v = Wx1[j]; dst = g_Wx1c; }
        else             { v = Wh1[j]; dst = g_Wh1c; }
        dst[j] = __uint_as_float(f2tf(v));
    }
}

__global__ void init_state_kernel() {
    int i = blockIdx.x * blockDim.x + threadIdx.x;
    if (i < BB * HH) {
        g_h0[0][i] = 0.f; g_h1[0][i] = 0.f;
        g_c0[i] = 0.f;    g_c1[i] = 0.f;
    }
}

// ---------------- precompute G0 = X @ Wx0 + b0, stored [T][B][4H] ----------------
// BM=128, BN=64, BK=16, 256 threads (8 warps: 2 M-warps x 4 N-warps)
__global__ void __launch_bounds__(256) xgemm_kernel(const float* __restrict__ x,
                                                    const float* __restrict__ b0) {
    __shared__ uint32_t sA[128][17];
    __shared__ float    sB[16][64];
    const int tid  = threadIdx.x;
    const int lane = tid & 31;
    const int warp = tid >> 5;
    const int warpM = warp & 1;
    const int warpN = warp >> 1;
    const int bm = blockIdx.y * 128;
    const int bn = blockIdx.x * 64;

    float acc[4][2][4];
#pragma unroll
    for (int i = 0; i < 4; i++)
#pragma unroll
        for (int j = 0; j < 2; j++)
#pragma unroll
            for (int p = 0; p < 4; p++) acc[i][j][p] = 0.f;

    const int arow = tid >> 1;
    const int acb  = (tid & 1) * 8;
    const int brow = tid >> 4;
    const int bcol = (tid & 15) * 4;

    for (int k0 = 0; k0 < DD; k0 += 16) {
        {
            const float* s = x + (size_t)(bm + arow) * DD + k0 + acb;
            float4 v0 = *(const float4*)s;
            float4 v1 = *(const float4*)(s + 4);
            sA[arow][acb + 0] = f2tf(v0.x); sA[arow][acb + 1] = f2tf(v0.y);
            sA[arow][acb + 2] = f2tf(v0.z); sA[arow][acb + 3] = f2tf(v0.w);
            sA[arow][acb + 4] = f2tf(v1.x); sA[arow][acb + 5] = f2tf(v1.y);
            sA[arow][acb + 6] = f2tf(v1.z); sA[arow][acb + 7] = f2tf(v1.w);
        }
        *(float4*)&sB[brow][bcol] =
            *(const float4*)(g_Wx0c + (size_t)(k0 + brow) * G4 + bn + bcol);
        __syncthreads();
#pragma unroll
        for (int ks = 0; ks < 2; ks++) {
            uint32_t a[4][4];
            const int kb = ks * 8 + (lane & 3);
#pragma unroll
            for (int mt = 0; mt < 4; mt++) {
                const int r = warpM * 64 + mt * 16 + (lane >> 2);
                a[mt][0] = sA[r][kb];     a[mt][1] = sA[r + 8][kb];
                a[mt][2] = sA[r][kb + 4]; a[mt][3] = sA[r + 8][kb + 4];
            }
#pragma unroll
            for (int nt = 0; nt < 2; nt++) {
                uint32_t b[2];
                const int c = warpN * 16 + nt * 8 + (lane >> 2);
                b[0] = __float_as_uint(sB[kb][c]);
                b[1] = __float_as_uint(sB[kb + 4][c]);
#pragma unroll
                for (int mt = 0; mt < 4; mt++) mma8(acc[mt][nt], a[mt], b);
            }
        }
        __syncthreads();
    }
#pragma unroll
    for (int mt = 0; mt < 4; mt++)
#pragma unroll
        for (int nt = 0; nt < 2; nt++)
#pragma unroll
            for (int p = 0; p < 4; p++) {
                int row = bm + warpM * 64 + mt * 16 + (lane >> 2) + ((p & 2) ? 8 : 0);
                int col = bn + warpN * 16 + nt * 8 + 2 * (lane & 3) + (p & 1);
                int b_ = row >> 8;      // batch (row = b*256 + t in x layout)
                int t_ = row & 255;     // time
                g_G0[(size_t)((t_ << 6) + b_) * G4 + col] = acc[mt][nt][p] + b0[col];
            }
}

// ---------------- fused LSTM cell: gates GEMM + activations ----------------
// 128 blocks x 128 threads. Block owns 8 h-columns -> 32 gate columns
// (order [i(8) f(8) g(8) o(8)], so n-tile index == gate type).
// Register-prefetch double-buffering over K (BK=32).
template <int LAYER>
__global__ void __launch_bounds__(128) cell_kernel(int t, const float* __restrict__ bias) {
    __shared__ uint32_t sA[64][33];
    __shared__ float    sB[32][32];
    const int tid  = threadIdx.x;
    const int lane = tid & 31;
    const int warp = tid >> 5;
    const int j0 = blockIdx.x * 8;

    float acc[4][4];
#pragma unroll
    for (int i = 0; i < 4; i++)
#pragma unroll
        for (int p = 0; p < 4; p++) acc[i][p] = 0.f;

    const int arow = tid >> 1;         // 0..63 (batch row)
    const int acb  = (tid & 1) * 16;   // 0 or 16
    const int bk   = tid >> 2;         // 0..31 (k within tile)
    const int bg   = tid & 3;          // gate

    const int NSEG = (LAYER == 0) ? 1 : 2;
    for (int seg = 0; seg < NSEG; seg++) {
        const float* Abase;
        const float* Wbase;
        if (LAYER == 0)      { Abase = g_h0[t & 1];       Wbase = g_Wh0c; }
        else if (seg == 0)   { Abase = g_h0[(t + 1) & 1]; Wbase = g_Wx1c; }
        else                 { Abase = g_h1[t & 1];       Wbase = g_Wh1c; }

        float4 pa0, pa1, pa2, pa3, pb0, pb1;
        {
            const float* s = Abase + arow * HH + acb;
            pa0 = *(const float4*)(s);     pa1 = *(const float4*)(s + 4);
            pa2 = *(const float4*)(s + 8); pa3 = *(const float4*)(s + 12);
            const float* w = Wbase + bk * G4 + bg * HH + j0;
            pb0 = *(const float4*)(w);     pb1 = *(const float4*)(w + 4);
        }
        for (int it = 0; it < 32; it++) {
            sA[arow][acb + 0]  = f2tf(pa0.x); sA[arow][acb + 1]  = f2tf(pa0.y);
            sA[arow][acb + 2]  = f2tf(pa0.z); sA[arow][acb + 3]  = f2tf(pa0.w);
            sA[arow][acb + 4]  = f2tf(pa1.x); sA[arow][acb + 5]  = f2tf(pa1.y);
            sA[arow][acb + 6]  = f2tf(pa1.z); sA[arow][acb + 7]  = f2tf(pa1.w);
            sA[arow][acb + 8]  = f2tf(pa2.x); sA[arow][acb + 9]  = f2tf(pa2.y);
            sA[arow][acb + 10] = f2tf(pa2.z); sA[arow][acb + 11] = f2tf(pa2.w);
            sA[arow][acb + 12] = f2tf(pa3.x); sA[arow][acb + 13] = f2tf(pa3.y);
            sA[arow][acb + 14] = f2tf(pa3.z); sA[arow][acb + 15] = f2tf(pa3.w);
            *(float4*)&sB[bk][bg * 8]     = pb0;
            *(float4*)&sB[bk][bg * 8 + 4] = pb1;
            __syncthreads();
            if (it + 1 < 32) {   // prefetch next K tile while MMAs run
                const int k0 = (it + 1) * 32;
                const float* s = Abase + arow * HH + k0 + acb;
                pa0 = *(const float4*)(s);     pa1 = *(const float4*)(s + 4);
                pa2 = *(const float4*)(s + 8); pa3 = *(const float4*)(s + 12);
                const float* w = Wbase + (k0 + bk) * G4 + bg * HH + j0;
                pb0 = *(const float4*)(w);     pb1 = *(const float4*)(w + 4);
            }
#pragma unroll
            for (int ks = 0; ks < 4; ks++) {
                uint32_t a[4];
                const int kb = ks * 8 + (lane & 3);
                const int r  = warp * 16 + (lane >> 2);
                a[0] = sA[r][kb];     a[1] = sA[r + 8][kb];
                a[2] = sA[r][kb + 4]; a[3] = sA[r + 8][kb + 4];
#pragma unroll
                for (int nt = 0; nt < 4; nt++) {
                    uint32_t b[2];
                    const int c = nt * 8 + (lane >> 2);
                    b[0] = __float_as_uint(sB[kb][c]);
                    b[1] = __float_as_uint(sB[kb + 4][c]);
                    mma8(acc[nt], a, b);
                }
            }
            __syncthreads();
        }
    }

    float* c_io  = (LAYER == 0) ? g_c0 : g_c1;
    float* h_out = (LAYER == 0) ? g_h0[(t + 1) & 1] : g_h1[(t + 1) & 1];
    const float* addG = g_G0 + (size_t)t * BB * G4;

#pragma unroll
    for (int p = 0; p < 4; p++) {
        const int row = warp * 16 + (lane >> 2) + ((p & 2) ? 8 : 0);
        const int col = j0 + 2 * (lane & 3) + (p & 1);
        float iv = acc[0][p], fv = acc[1][p], gv = acc[2][p], ov = acc[3][p];
        if (LAYER == 0) {
            const float* gr = addG + (size_t)row * G4;
            iv += gr[col]; fv += gr[col + 1024]; gv += gr[col + 2048]; ov += gr[col + 3072];
        } else {
            iv += bias[col]; fv += bias[col + 1024]; gv += bias[col + 2048]; ov += bias[col + 3072];
        }
        const float si = sigf(iv), sf = sigf(fv), so = sigf(ov);
        const float tg = tanhf_(gv);
        const int idx = row * HH + col;
        const float cn = sf * c_io[idx] + si * tg;
        c_io[idx]  = cn;
        h_out[idx] = so * tanhf_(cn);
    }
}

__global__ void copy_out_kernel(float* __restrict__ out) {
    int i = blockIdx.x * blockDim.x + threadIdx.x;
    if (i < BB * HH) out[i] = g_h1[0][i];   // t=255 wrote buffer (255+1)&1 == 0
}

// ---------------- launch ----------------
extern "C" void kernel_launch(void* const* d_in, const int* in_sizes, int n_in,
                              void* d_out, int out_size) {
    const float* x   = (const float*)d_in[0];
    const float* Wx0 = (const float*)d_in[1];
    const float* Wh0 = (const float*)d_in[2];
    const float* b0  = (const float*)d_in[3];
    const float* Wx1 = (const float*)d_in[4];
    const float* Wh1 = (const float*)d_in[5];
    const float* b1  = (const float*)d_in[6];
    (void)in_sizes; (void)n_in; (void)out_size;

    convert_all_kernel<<<4096, 256>>>(Wx0, Wh0, Wx1, Wh1);
    init_state_kernel<<<(BB * HH + 255) / 256, 256>>>();

    dim3 grid_x(G4 / 64, (BB * TT) / 128);   // (64, 128)
    xgemm_kernel<<<grid_x, 256>>>(x, b0);

    for (int t = 0; t < TT; t++) {
        cell_kernel<0><<<128, 128>>>(t, nullptr);
        cell_kernel<1><<<128, 128>>>(t, b1);
    }
    copy_out_kernel<<<(BB * HH + 255) / 256, 256>>>((float*)d_out);
}

// round 2
// speedup vs baseline: 2.3166x; 2.3166x over previous
#include <cuda_runtime.h>
#include <cstdint>
#include <cstddef>

#define BB   64
#define TT   256
#define DD   1024
#define HH   1024
#define G4   4096
#define NB   128     // persistent blocks, one 32-gate-col tile each

// ---------------- device scratch ----------------
__device__ float g_G0p[(size_t)TT * NB * 64 * 32];  // packed [t][bn][row(64)][32]
__device__ float g_Wx0c[DD * G4];                   // tf32-rounded, [k][4096] for xgemm
__device__ float g_Wh0p[HH * G4];                   // packed [bn][kt][col32][kin64]
__device__ float g_Wx1p[HH * G4];
__device__ float g_Wh1p[HH * G4];
__device__ float g_b1p[NB * 32];
__device__ float g_h0r[2][BB * HH];                 // tf32-rounded hidden (ping-pong)
__device__ float g_h1r[2][BB * HH];
__device__ float g_h1e[BB * HH];                    // exact h1 for output
__device__ unsigned g_bar;

// ---------------- smem layout (bytes) ----------------
// A tile: 64 rows x 68 floats (pad) = 17408B ; B tile: 32 cols x 68 = 8704B
// stage = 2 groups x (A + B) = 52224B ; 3 stages + G0 (8KB) + reduce (8KB)
#define SA_OFF(s,g)  ((s)*52224 + (g)*17408)
#define SB_OFF(s,g)  ((s)*52224 + 34816 + (g)*8704)
#define SG0_OFF      156672
#define SRED_OFF     164864
#define SMEM_BYTES   173056

// ---------------- helpers ----------------
__device__ __forceinline__ uint32_t f2tf(float x) {
    uint32_t r; asm("cvt.rna.tf32.f32 %0, %1;" : "=r"(r) : "f"(x)); return r;
}
__device__ __forceinline__ void mma8(float* d, const uint32_t* a, const uint32_t* b) {
    asm volatile(
        "mma.sync.aligned.m16n8k8.row.col.f32.tf32.tf32.f32 "
        "{%0,%1,%2,%3}, {%4,%5,%6,%7}, {%8,%9}, {%0,%1,%2,%3};"
        : "+f"(d[0]), "+f"(d[1]), "+f"(d[2]), "+f"(d[3])
        : "r"(a[0]), "r"(a[1]), "r"(a[2]), "r"(a[3]), "r"(b[0]), "r"(b[1]));
}
__device__ __forceinline__ void cp16(uint32_t s, const void* g) {
    asm volatile("cp.async.cg.shared.global [%0], [%1], 16;" :: "r"(s), "l"(g));
}
#define CP_COMMIT() asm volatile("cp.async.commit_group;")
#define CP_WAIT1()  asm volatile("cp.async.wait_group 1;")

__device__ __forceinline__ float sigf(float x)   { return 1.f / (1.f + __expf(-x)); }
__device__ __forceinline__ float tanhf_(float x) { return 2.f / (1.f + __expf(-2.f * x)) - 1.f; }

__device__ __forceinline__ void gridbar(unsigned target) {
    __syncthreads();
    if (threadIdx.x == 0) {
        __threadfence();
        atomicAdd(&g_bar, 1u);
        while (*(volatile unsigned*)&g_bar < target) {}
        __threadfence();
    }
    __syncthreads();
}

// ---------------- convert + pack weights ----------------
__global__ void convert_pack_kernel(const float* __restrict__ Wx0, const float* __restrict__ Wh0,
                                    const float* __restrict__ Wx1, const float* __restrict__ Wh1,
                                    const float* __restrict__ b1) {
    const int n1 = 1 << 22;
    const int stride = gridDim.x * blockDim.x;
    for (int idx = blockIdx.x * blockDim.x + threadIdx.x; idx < 4 * n1; idx += stride) {
        int w = idx >> 22;
        int d = idx & (n1 - 1);
        if (w == 0) {
            g_Wx0c[d] = __uint_as_float(f2tf(Wx0[d]));
        } else {
            int kin = d & 63, c = (d >> 6) & 31, kt = (d >> 11) & 15, bn = d >> 15;
            int gate = c >> 3, cw = c & 7;
            int src = (kt * 64 + kin) * G4 + gate * HH + bn * 8 + cw;
            float v = (w == 1) ? Wh0[src] : (w == 2) ? Wx1[src] : Wh1[src];
            float* dst = (w == 1) ? g_Wh0p : (w == 2) ? g_Wx1p : g_Wh1p;
            dst[d] = __uint_as_float(f2tf(v));
        }
    }
    for (int i = blockIdx.x * blockDim.x + threadIdx.x; i < NB * 32; i += stride) {
        int bn = i >> 5, c = i & 31, gate = c >> 3, cw = c & 7;
        g_b1p[i] = b1[gate * HH + bn * 8 + cw];
    }
}

__global__ void init_kernel() {
    int i = blockIdx.x * blockDim.x + threadIdx.x;
    if (i < BB * HH) {
        g_h0r[0][i] = 0.f; g_h0r[1][i] = 0.f;
        g_h1r[0][i] = 0.f; g_h1r[1][i] = 0.f;
    }
    if (i == 0) g_bar = 0u;
}

// ---------------- precompute G0 = X @ Wx0 + b0 into packed layout ----------------
__global__ void __launch_bounds__(256) xgemm_kernel(const float* __restrict__ x,
                                                    const float* __restrict__ b0) {
    __shared__ uint32_t sA[128][17];
    __shared__ float    sB[16][64];
    const int tid  = threadIdx.x;
    const int lane = tid & 31;
    const int warp = tid >> 5;
    const int warpM = warp & 1;
    const int warpN = warp >> 1;
    const int bm = blockIdx.y * 128;
    const int bn = blockIdx.x * 64;

    float acc[4][2][4];
#pragma unroll
    for (int i = 0; i < 4; i++)
#pragma unroll
        for (int j = 0; j < 2; j++)
#pragma unroll
            for (int p = 0; p < 4; p++) acc[i][j][p] = 0.f;

    const int arow = tid >> 1;
    const int acb  = (tid & 1) * 8;
    const int brow = tid >> 4;
    const int bcol = (tid & 15) * 4;

    for (int k0 = 0; k0 < DD; k0 += 16) {
        {
            const float* s = x + (size_t)(bm + arow) * DD + k0 + acb;
            float4 v0 = *(const float4*)s;
            float4 v1 = *(const float4*)(s + 4);
            sA[arow][acb + 0] = f2tf(v0.x); sA[arow][acb + 1] = f2tf(v0.y);
            sA[arow][acb + 2] = f2tf(v0.z); sA[arow][acb + 3] = f2tf(v0.w);
            sA[arow][acb + 4] = f2tf(v1.x); sA[arow][acb + 5] = f2tf(v1.y);
            sA[arow][acb + 6] = f2tf(v1.z); sA[arow][acb + 7] = f2tf(v1.w);
        }
        *(float4*)&sB[brow][bcol] =
            *(const float4*)(g_Wx0c + (size_t)(k0 + brow) * G4 + bn + bcol);
        __syncthreads();
#pragma unroll
        for (int ks = 0; ks < 2; ks++) {
            uint32_t a[4][4];
            const int kb = ks * 8 + (lane & 3);
#pragma unroll
            for (int mt = 0; mt < 4; mt++) {
                const int r = warpM * 64 + mt * 16 + (lane >> 2);
                a[mt][0] = sA[r][kb];     a[mt][1] = sA[r + 8][kb];
                a[mt][2] = sA[r][kb + 4]; a[mt][3] = sA[r + 8][kb + 4];
            }
#pragma unroll
            for (int nt = 0; nt < 2; nt++) {
                uint32_t b[2];
                const int c = warpN * 16 + nt * 8 + (lane >> 2);
                b[0] = __float_as_uint(sB[kb][c]);
                b[1] = __float_as_uint(sB[kb + 4][c]);
#pragma unroll
                for (int mt = 0; mt < 4; mt++) mma8(acc[mt][nt], a[mt], b);
            }
        }
        __syncthreads();
    }
#pragma unroll
    for (int mt = 0; mt < 4; mt++)
#pragma unroll
        for (int nt = 0; nt < 2; nt++)
#pragma unroll
            for (int p = 0; p < 4; p++) {
                int row = bm + warpM * 64 + mt * 16 + (lane >> 2) + ((p & 2) ? 8 : 0);
                int col = bn + warpN * 16 + nt * 8 + 2 * (lane & 3) + (p & 1);
                int b_ = row >> 8;       // batch
                int t_ = row & 255;      // time
                int gate = col >> 10, within = col & 1023;
                int bnp = within >> 3, cwi = within & 7;
                g_G0p[(((size_t)t_ * NB + bnp) * 64 + b_) * 32 + gate * 8 + cwi] =
                    acc[mt][nt][p] + __ldg(&b0[col]);
            }
}

// ---------------- persistent LSTM recurrence ----------------
template <int PHASE>
__device__ __forceinline__ void load_stage(uint32_t sbase, int slot, int i, int bn, int tid,
                                           const float* Ag0, const float* Ag1,
                                           const float* Wg0, const float* Wg1) {
#pragma unroll
    for (int g = 0; g < 2; g++) {
        const float* Asrc; const float* Bsrc;
        if (PHASE == 0) {
            Asrc = Ag0 + (g * 512 + i * 64);
            Bsrc = Wg0 + (size_t)(bn * 16 + g * 8 + i) * 2048;
        } else {
            Asrc = (g == 0 ? Ag0 : Ag1) + i * 64;
            Bsrc = (g == 0 ? Wg0 : Wg1) + (size_t)(bn * 16 + i) * 2048;
        }
        uint32_t sa = sbase + SA_OFF(slot, g);
        uint32_t sb = sbase + SB_OFF(slot, g);
#pragma unroll
        for (int j = 0; j < 4; j++) {
            int c = j * 256 + tid; int row = c >> 4; int kc = c & 15;
            cp16(sa + row * 272 + kc * 16, Asrc + (size_t)row * HH + kc * 4);
        }
#pragma unroll
        for (int j = 0; j < 2; j++) {
            int c = j * 256 + tid;
            cp16(sb + (c >> 4) * 272 + (c & 15) * 16, Bsrc + c * 4);
        }
    }
}

__device__ __forceinline__ void mma_stage(const float* smemf, int slot, int wm, int wk,
                                          int lane, float acc[4][4]) {
    const float* A  = smemf + (SA_OFF(slot, wk) >> 2);
    const float* Bp = smemf + (SB_OFF(slot, wk) >> 2);
    const int l2 = lane >> 2, la3 = lane & 3;
    const int r0 = (wm * 16 + l2) * 68;
    const int r1 = r0 + 8 * 68;
#pragma unroll
    for (int ks = 0; ks < 8; ks++) {
        const int kb = ks * 8 + la3;
        uint32_t a[4];
        a[0] = __float_as_uint(A[r0 + kb]);
        a[1] = __float_as_uint(A[r1 + kb]);
        a[2] = __float_as_uint(A[r0 + kb + 4]);
        a[3] = __float_as_uint(A[r1 + kb + 4]);
#pragma unroll
        for (int nt = 0; nt < 4; nt++) {
            uint32_t b[2];
            b[0] = __float_as_uint(Bp[(nt * 8 + l2) * 68 + kb]);
            b[1] = __float_as_uint(Bp[(nt * 8 + l2) * 68 + kb + 4]);
            mma8(acc[nt], a, b);
        }
    }
}

template <int PHASE>
__device__ __forceinline__ void run_phase(float* smemf, uint32_t sbase, int t, int bn,
                                          int tid, int lane, int wm, int wk,
                                          const float* Ag0, const float* Ag1,
                                          const float* Wg0, const float* Wg1,
                                          float* h_out, float* cc) {
    constexpr int NIT = (PHASE == 0) ? 8 : 16;
    float acc[4][4];
#pragma unroll
    for (int n = 0; n < 4; n++)
#pragma unroll
        for (int p = 0; p < 4; p++) acc[n][p] = 0.f;

    load_stage<PHASE>(sbase, 0, 0, bn, tid, Ag0, Ag1, Wg0, Wg1);
    if (PHASE == 0) {
        const float* g0src = g_G0p + ((size_t)t * NB + bn) * 2048;
#pragma unroll
        for (int j = 0; j < 2; j++) {
            int c = j * 256 + tid;
            cp16(sbase + SG0_OFF + c * 16, g0src + c * 4);
        }
    }
    CP_COMMIT();
    load_stage<PHASE>(sbase, 1, 1, bn, tid, Ag0, Ag1, Wg0, Wg1);
    CP_COMMIT();

    for (int i = 0; i < NIT; i++) {
        CP_WAIT1();
        __syncthreads();
        if (i + 2 < NIT) load_stage<PHASE>(sbase, (i + 2) % 3, i + 2, bn, tid, Ag0, Ag1, Wg0, Wg1);
        CP_COMMIT();
        mma_stage(smemf, i % 3, wm, wk, lane, acc);
    }
    __syncthreads();

    float* red = smemf + (SRED_OFF >> 2);
    if (wk == 1) {
#pragma unroll
        for (int n = 0; n < 4; n++)
#pragma unroll
            for (int p = 0; p < 4; p++)
                red[(wm * 32 + lane) * 16 + n * 4 + p] = acc[n][p];
    }
    __syncthreads();
    if (wk == 0) {
#pragma unroll
        for (int n = 0; n < 4; n++)
#pragma unroll
            for (int p = 0; p < 4; p++)
                acc[n][p] += red[(wm * 32 + lane) * 16 + n * 4 + p];

        const float* g0f = smemf + (SG0_OFF >> 2);
        const int l2 = lane >> 2, la3 = lane & 3;
#pragma unroll
        for (int p = 0; p < 4; p++) {
            int row = wm * 16 + l2 + ((p & 2) ? 8 : 0);
            int cwi = 2 * la3 + (p & 1);
            float iv = acc[0][p], fv = acc[1][p], gv = acc[2][p], ov = acc[3][p];
            if (PHASE == 0) {
                iv += g0f[row * 32 + cwi];      fv += g0f[row * 32 + 8 + cwi];
                gv += g0f[row * 32 + 16 + cwi]; ov += g0f[row * 32 + 24 + cwi];
            } else {
                iv += __ldg(&g_b1p[bn * 32 + cwi]);      fv += __ldg(&g_b1p[bn * 32 + 8 + cwi]);
                gv += __ldg(&g_b1p[bn * 32 + 16 + cwi]); ov += __ldg(&g_b1p[bn * 32 + 24 + cwi]);
            }
            float si = sigf(iv), sf = sigf(fv), so = sigf(ov);
            float tg = tanhf_(gv);
            float cn = sf * cc[p] + si * tg;
            cc[p] = cn;
            float h = so * tanhf_(cn);
            int col = bn * 8 + cwi;
            h_out[row * HH + col] = __uint_as_float(f2tf(h));
            if (PHASE == 1) g_h1e[row * HH + col] = h;
        }
    }
}

__global__ void __launch_bounds__(256, 1) lstm_persist() {
    extern __shared__ float smemf[];
    uint32_t sbase = (uint32_t)__cvta_generic_to_shared(smemf);
    const int tid = threadIdx.x, lane = tid & 31, warp = tid >> 5;
    const int wm = warp & 3, wk = warp >> 2;
    const int bn = blockIdx.x;

    float c0r[4] = {0.f, 0.f, 0.f, 0.f};
    float c1r[4] = {0.f, 0.f, 0.f, 0.f};
    unsigned tgt = 0;

    for (int t = 0; t < TT; t++) {
        run_phase<0>(smemf, sbase, t, bn, tid, lane, wm, wk,
                     g_h0r[t & 1], nullptr, g_Wh0p, nullptr,
                     g_h0r[(t + 1) & 1], c0r);
        tgt += NB; gridbar(tgt);
        run_phase<1>(smemf, sbase, t, bn, tid, lane, wm, wk,
                     g_h0r[(t + 1) & 1], g_h1r[t & 1], g_Wx1p, g_Wh1p,
                     g_h1r[(t + 1) & 1], c1r);
        tgt += NB; gridbar(tgt);
    }
}

__global__ void copy_out_kernel(float* __restrict__ out) {
    int i = blockIdx.x * blockDim.x + threadIdx.x;
    if (i < BB * HH) out[i] = g_h1e[i];
}

// ---------------- launch ----------------
extern "C" void kernel_launch(void* const* d_in, const int* in_sizes, int n_in,
                              void* d_out, int out_size) {
    const float* x   = (const float*)d_in[0];
    const float* Wx0 = (const float*)d_in[1];
    const float* Wh0 = (const float*)d_in[2];
    const float* b0  = (const float*)d_in[3];
    const float* Wx1 = (const float*)d_in[4];
    const float* Wh1 = (const float*)d_in[5];
    const float* b1  = (const float*)d_in[6];
    (void)in_sizes; (void)n_in; (void)out_size;

    cudaFuncSetAttribute(lstm_persist, cudaFuncAttributeMaxDynamicSharedMemorySize, SMEM_BYTES);

    convert_pack_kernel<<<4096, 256>>>(Wx0, Wh0, Wx1, Wh1, b1);
    init_kernel<<<256, 256>>>();

    dim3 grid_x(G4 / 64, (BB * TT) / 128);
    xgemm_kernel<<<grid_x, 256>>>(x, b0);

    lstm_persist<<<NB, 256, SMEM_BYTES>>>();

    copy_out_kernel<<<(BB * HH + 255) / 256, 256>>>((float*)d_out);
}